// round 8
// baseline (speedup 1.0000x reference)
#include <cuda_runtime.h>

#define LAYERS 12
#define NROW   4096
#define DD     16
#define TPB    256
#define QPT    4                                   // quarter-rows per thread
#define NBLK   192                                 // 16 blocks per layer
#define BLK_PER_LAYER (NBLK / LAYERS)              // 16
#define NWARP  (TPB / 32)
#define FULL   0xffffffffu

// Per-block partials, plain stores (overwritten every replay, no reset needed).
// Layout: [0..15]=sum p, [16..31]=sum v, [32]=sum diag, [33]=sum log(s).
__device__ float        g_part[NBLK][34];
__device__ unsigned int g_ticket;   // reset to 0 by the finalizing block

__global__ void __launch_bounds__(TPB) fused_kernel(const float* __restrict__ x,
                                                    float* __restrict__ out) {
    const int tid  = threadIdx.x;
    const int lane = tid & 31;
    const int wid  = tid >> 5;

    // Block covers 256 rows = 1024 quarter-rows; thread takes 4 at stride 256,
    // so its sub-position within every row is lane&3.
    const int qbase = blockIdx.x * (TPB * QPT) + tid;
    float4 a[QPT];
#pragma unroll
    for (int k = 0; k < QPT; k++)
        a[k] = reinterpret_cast<const float4*>(x)[qbase + k * TPB];

    // No max-subtract: inputs are N(0,1); exp() cannot overflow fp32.
    float r[8];                 // [0..3] = sum_k p[d], [4..7] = sum_k v[d]
    float diag  = 0.f;          // lane-local sum p*log_q
    float lgsum = 0.f;          // sum log(s), kept by lane&3==0
#pragma unroll
    for (int i = 0; i < 4; i++) r[i] = r[i + 4] = 0.f;

#pragma unroll
    for (int k = 0; k < QPT; k++) {
        float v[4] = { a[k].x, a[k].y, a[k].z, a[k].w };
        float e[4];
        float u = 0.f, t = 0.f;
#pragma unroll
        for (int i = 0; i < 4; i++) {
            e[i] = __expf(v[i]);
            u += e[i];
            t = fmaf(e[i], v[i], t);           // lane-local sum e*v
        }
        float s = u;                            // row sum across 4 lanes
        s += __shfl_xor_sync(FULL, s, 1);
        s += __shfl_xor_sync(FULL, s, 2);
        const float inv = 1.0f / s;
        const float lg  = __logf(s);

        diag = fmaf(inv, t - lg * u, diag);     // sum_i p*(v - log s)
        if ((lane & 3) == 0) lgsum += lg;

#pragma unroll
        for (int i = 0; i < 4; i++) {
            r[i]     = fmaf(e[i], inv, r[i]);
            r[i + 4] += v[i];
        }
    }

    // ---- recursive-halving warp reduce: 8 regs over masks {4,8,16} ----
    float t4[4];
    {
        const bool up = (lane & 4) != 0;
#pragma unroll
        for (int i = 0; i < 4; i++) {
            float snd  = up ? r[i] : r[i + 4];
            float recv = __shfl_xor_sync(FULL, snd, 4);
            t4[i] = (up ? r[i + 4] : r[i]) + recv;
        }
    }
    float t2[2];
    {
        const bool up = (lane & 8) != 0;
#pragma unroll
        for (int i = 0; i < 2; i++) {
            float snd  = up ? t4[i] : t4[i + 2];
            float recv = __shfl_xor_sync(FULL, snd, 8);
            t2[i] = (up ? t4[i + 2] : t4[i]) + recv;
        }
    }
    float t1;
    {
        const bool up = (lane & 16) != 0;
        float snd  = up ? t2[0] : t2[1];
        float recv = __shfl_xor_sync(FULL, snd, 16);
        t1 = (up ? t2[1] : t2[0]) + recv;
    }
#pragma unroll
    for (int off = 16; off > 0; off >>= 1) {
        diag  += __shfl_xor_sync(FULL, diag,  off);
        lgsum += __shfl_xor_sync(FULL, lgsum, off);
    }

    const int istar = (((lane >> 2) & 1) << 2) | (((lane >> 3) & 1) << 1) | ((lane >> 4) & 1);
    const int S     = ((istar & 4) ? DD : 0) + (lane & 3) * 4 + (istar & 3);

    __shared__ float smem[NWARP][36];
    smem[wid][S] = t1;
    if (lane == 0) { smem[wid][32] = diag; smem[wid][33] = lgsum; }
    __syncthreads();

    if (tid < 34) {
        float acc = 0.f;
#pragma unroll
        for (int w = 0; w < NWARP; w++) acc += smem[w][tid];
        g_part[blockIdx.x][tid] = acc;          // plain store
        __threadfence();                        // order store before ticket
    }
    __syncthreads();

    // ---- ticket: last arriving block finalizes ----
    __shared__ unsigned int s_last;
    if (tid == 0)
        s_last = (atomicAdd(&g_ticket, 1u) == (unsigned)(NBLK - 1));
    __syncthreads();
    if (!s_last) return;
    __threadfence();                            // acquire all partials

    // Phase 1: 408 (layer,slot) sums of 16 partials, spread over 256 thr x 2.
    __shared__ float s_acc[LAYERS][34];
#pragma unroll
    for (int it = 0; it < 2; it++) {
        const int idx = tid + it * TPB;
        if (idx < LAYERS * 34) {
            const int layer = idx / 34;
            const int slot  = idx - layer * 34;
            float acc = 0.f;
#pragma unroll
            for (int b = 0; b < BLK_PER_LAYER; b++)
                acc += __ldcg(&g_part[layer * BLK_PER_LAYER + b][slot]);
            s_acc[layer][slot] = acc;
        }
    }
    __syncthreads();

    // Phase 2: one warp computes the scalar loss.
    if (tid < 32) {
        float a1 = 0.f, a2 = 0.f;
        if (lane < LAYERS) {
            const float lgs = s_acc[lane][33];          // sum over rows of log(s)
            float sp[DD], dot = 0.f, spt = 0.f;
#pragma unroll
            for (int d = 0; d < DD; d++) {
                sp[d] = s_acc[lane][d];
                float slq = s_acc[lane][DD + d] - lgs;  // sum log_q[d]
                dot += sp[d] * slq;
                spt += sp[d];
            }
            a1 = dot - s_acc[lane][32];
            const float invt = 1.0f / spt;
            float ls = 0.f;
#pragma unroll
            for (int d = 0; d < DD; d++)
                ls += __logf(sp[d] * invt + 1e-8f);
            a2 = -ls / (float)DD;
        }
#pragma unroll
        for (int off = 16; off > 0; off >>= 1) {
            a1 += __shfl_xor_sync(FULL, a1, off);
            a2 += __shfl_xor_sync(FULL, a2, off);
        }
        if (lane == 0) {
            const float aux1 = a1 / (2.0f * (float)LAYERS);
            const float aux2 = a2 / (float)LAYERS;
            out[0] = 0.01f * (aux1 + aux2);     // ALPHA*(BETA*aux1 + aux2)
            g_ticket = 0u;                      // ready for next replay
        }
    }
}

extern "C" void kernel_launch(void* const* d_in, const int* in_sizes, int n_in,
                              void* d_out, int out_size) {
    fused_kernel<<<NBLK, TPB>>>((const float*)d_in[0], (float*)d_out);
}

// round 9
// speedup vs baseline: 1.0286x; 1.0286x over previous
#include <cuda_runtime.h>

#define LAYERS 12
#define NROW   4096
#define DD     16
#define TPB    256
#define QPT    4                                   // quarter-rows per thread
#define NBLK   192                                 // 16 blocks per layer
#define NWARP  (TPB / 32)
#define FULL   0xffffffffu

// Per-layer accumulators, padded to 36 floats (144B, 16B-aligned rows) so the
// finalize kernel can read each row with 9 x LDG.128.
// Slots: [0..15]=sum p, [16..31]=sum v, [32]=sum diag, [33]=sum log(s).
// Zero at module load; finalize_kernel re-zeroes after use so every graph
// replay is deterministic.
__device__ __align__(16) float g_acc[LAYERS][36];

// ---------------------------------------------------------------------------
// Kernel 1: accumulate per-layer sums (lean body, atomics, no fences — PDL's
// implicit completion trigger flushes memory before finalize proceeds).
// ---------------------------------------------------------------------------
__global__ void __launch_bounds__(TPB) accum_kernel(const float* __restrict__ x) {
    const int tid   = threadIdx.x;
    const int lane  = tid & 31;
    const int wid   = tid >> 5;
    const int layer = blockIdx.x >> 4;              // 16 blocks per layer, uniform

    // 4 quarter-rows from 4 independent rows; sub-position within row = lane&3.
    const int qbase = blockIdx.x * (TPB * QPT) + tid;
    float4 a[QPT];
#pragma unroll
    for (int k = 0; k < QPT; k++)
        a[k] = reinterpret_cast<const float4*>(x)[qbase + k * TPB];

    // No max-subtract: inputs are N(0,1); exp() cannot overflow fp32.
    float r[8];                 // [0..3] = sum_k p[d], [4..7] = sum_k v[d]
    float diag  = 0.f;          // lane-local sum p*log_q
    float lgsum = 0.f;          // sum log(s), kept by lane&3==0
#pragma unroll
    for (int i = 0; i < 4; i++) r[i] = r[i + 4] = 0.f;

#pragma unroll
    for (int k = 0; k < QPT; k++) {
        float v[4] = { a[k].x, a[k].y, a[k].z, a[k].w };
        float e[4];
        float u = 0.f, t = 0.f;
#pragma unroll
        for (int i = 0; i < 4; i++) {
            e[i] = __expf(v[i]);
            u += e[i];
            t = fmaf(e[i], v[i], t);          // lane-local sum e*v
        }
        float s = u;                           // row sum across 4 lanes
        s += __shfl_xor_sync(FULL, s, 1);
        s += __shfl_xor_sync(FULL, s, 2);
        const float inv = 1.0f / s;
        const float lg  = __logf(s);

        diag = fmaf(inv, t - lg * u, diag);    // sum_i p*(v - log s)
        if ((lane & 3) == 0) lgsum += lg;

#pragma unroll
        for (int i = 0; i < 4; i++) {
            r[i]     = fmaf(e[i], inv, r[i]);  // p accumulation
            r[i + 4] += v[i];                   // raw logit accumulation
        }
    }

    // ---- recursive-halving warp reduce: 8 regs over masks {4,8,16} ----
    float t4[4];
    {
        const bool up = (lane & 4) != 0;
#pragma unroll
        for (int i = 0; i < 4; i++) {
            float snd  = up ? r[i] : r[i + 4];
            float recv = __shfl_xor_sync(FULL, snd, 4);
            t4[i] = (up ? r[i + 4] : r[i]) + recv;
        }
    }
    float t2[2];
    {
        const bool up = (lane & 8) != 0;
#pragma unroll
        for (int i = 0; i < 2; i++) {
            float snd  = up ? t4[i] : t4[i + 2];
            float recv = __shfl_xor_sync(FULL, snd, 8);
            t2[i] = (up ? t4[i + 2] : t4[i]) + recv;
        }
    }
    float t1;
    {
        const bool up = (lane & 16) != 0;
        float snd  = up ? t2[0] : t2[1];
        float recv = __shfl_xor_sync(FULL, snd, 16);
        t1 = (up ? t2[1] : t2[0]) + recv;
    }
    // diag + lgsum: 5-stage butterfly
#pragma unroll
    for (int off = 16; off > 0; off >>= 1) {
        diag  += __shfl_xor_sync(FULL, diag,  off);
        lgsum += __shfl_xor_sync(FULL, lgsum, off);
    }

    // lane -> sum slot
    const int istar = (((lane >> 2) & 1) << 2) | (((lane >> 3) & 1) << 1) | ((lane >> 4) & 1);
    const int S     = ((istar & 4) ? DD : 0) + (lane & 3) * 4 + (istar & 3);

    __shared__ float smem[NWARP][38];
    smem[wid][S] = t1;
    if (lane == 0) { smem[wid][32] = diag; smem[wid][33] = lgsum; }
    __syncthreads();

    if (tid < 34) {
        float acc = 0.f;
#pragma unroll
        for (int w = 0; w < NWARP; w++) acc += smem[w][tid];
        atomicAdd(&g_acc[layer][tid], acc);
    }
}

// ---------------------------------------------------------------------------
// Kernel 2: finalize, PDL. Ramps during accum, waits for grid completion
// (implicit trigger => memory visible), computes the scalar, re-zeroes.
// ---------------------------------------------------------------------------
__global__ void finalize_kernel(float* __restrict__ out) {
    asm volatile("griddepcontrol.wait;" ::: "memory");

    const int lane = threadIdx.x;   // one warp
    float a1 = 0.f, a2 = 0.f;
    if (lane < LAYERS) {
        // Load the whole 36-float row with 9 x LDG.128 (MLP=9).
        float row[36];
        const float4* rp = reinterpret_cast<const float4*>(&g_acc[lane][0]);
#pragma unroll
        for (int i = 0; i < 9; i++) {
            float4 q = __ldcg(&rp[i]);
            row[4*i+0] = q.x; row[4*i+1] = q.y; row[4*i+2] = q.z; row[4*i+3] = q.w;
        }
        const float lgs = row[33];                 // sum over rows of log(s)
        float dot = 0.f, spt = 0.f;
#pragma unroll
        for (int d = 0; d < DD; d++) {
            float sp  = row[d];
            float slq = row[DD + d] - lgs;         // sum log_q[d]
            dot += sp * slq;
            spt += sp;
        }
        a1 = dot - row[32];
        const float invt = 1.0f / spt;
        float ls = 0.f;
#pragma unroll
        for (int d = 0; d < DD; d++)
            ls += __logf(row[d] * invt + 1e-8f);
        a2 = -ls / (float)DD;
    }
#pragma unroll
    for (int off = 16; off > 0; off >>= 1) {
        a1 += __shfl_xor_sync(FULL, a1, off);
        a2 += __shfl_xor_sync(FULL, a2, off);
    }
    if (lane == 0) {
        const float aux1 = a1 / (2.0f * (float)LAYERS);
        const float aux2 = a2 / (float)LAYERS;
        out[0] = 0.01f * (aux1 + aux2);    // ALPHA*(BETA*aux1 + aux2)
    }

    // All lanes done reading; vectorized re-zero for the next graph replay.
    __syncwarp();
    float4* gz = reinterpret_cast<float4*>(&g_acc[0][0]);
    const float4 z = make_float4(0.f, 0.f, 0.f, 0.f);
#pragma unroll
    for (int i = lane; i < LAYERS * 36 / 4; i += 32)
        gz[i] = z;
}

extern "C" void kernel_launch(void* const* d_in, const int* in_sizes, int n_in,
                              void* d_out, int out_size) {
    const float* x = (const float*)d_in[0];
    float* out = (float*)d_out;

    accum_kernel<<<NBLK, TPB>>>(x);

    // Programmatic Dependent Launch: finalize's launch/ramp overlaps accum.
    cudaLaunchConfig_t cfg = {};
    cfg.gridDim  = dim3(1, 1, 1);
    cfg.blockDim = dim3(32, 1, 1);
    cfg.dynamicSmemBytes = 0;
    cfg.stream = 0;
    cudaLaunchAttribute attr[1];
    attr[0].id = cudaLaunchAttributeProgrammaticStreamSerialization;
    attr[0].val.programmaticStreamSerializationAllowed = 1;
    cfg.attrs = attr;
    cfg.numAttrs = 1;
    cudaLaunchKernelEx(&cfg, finalize_kernel, out);
}